// round 1
// baseline (speedup 1.0000x reference)
#include <cuda_runtime.h>
#include <cuda_bf16.h>
#include <cstdint>

// GraphAttentionPooling:
//   x: [B=196608, F=256] f32, grouped into G=65536 groups of P=3 rows.
//   scores[g,p] = dot(x[g,p,:], w) (+bias, softmax-invariant)
//   att = softmax over p; out[g,f] = sum_p att[p] * x[g,p,f]
//
// One warp per group. Lane l owns float4 chunks l and l+32 of each 256-float row.
// All 6 row-loads issued up front (MLP~6), dot via shfl_xor butterfly,
// 3-way softmax redundantly per lane, 2x STG.128 out.

#define F 256
#define P 3
#define F4 (F / 4)            // 64 float4 per row
#define WARPS_PER_BLOCK 8
#define THREADS (WARPS_PER_BLOCK * 32)

__global__ __launch_bounds__(THREADS)
void gap_kernel(const float* __restrict__ x,
                const float* __restrict__ w,
                float* __restrict__ out,
                int G)
{
    const int warp_global = (blockIdx.x * WARPS_PER_BLOCK) + (threadIdx.x >> 5);
    const int lane = threadIdx.x & 31;
    if (warp_global >= G) return;

    const size_t base = (size_t)warp_global * (size_t)(P * F);
    const float4* __restrict__ xr = reinterpret_cast<const float4*>(x + base);
    const float4* __restrict__ w4 = reinterpret_cast<const float4*>(w);

    // Front-batch all global loads for max MLP.
    float4 r00 = xr[0 * F4 + lane];
    float4 r01 = xr[0 * F4 + lane + 32];
    float4 r10 = xr[1 * F4 + lane];
    float4 r11 = xr[1 * F4 + lane + 32];
    float4 r20 = xr[2 * F4 + lane];
    float4 r21 = xr[2 * F4 + lane + 32];
    float4 w0  = __ldg(&w4[lane]);
    float4 w1  = __ldg(&w4[lane + 32]);

    // Per-row partial dot products.
    float d0 = r00.x * w0.x + r00.y * w0.y + r00.z * w0.z + r00.w * w0.w
             + r01.x * w1.x + r01.y * w1.y + r01.z * w1.z + r01.w * w1.w;
    float d1 = r10.x * w0.x + r10.y * w0.y + r10.z * w0.z + r10.w * w0.w
             + r11.x * w1.x + r11.y * w1.y + r11.z * w1.z + r11.w * w1.w;
    float d2 = r20.x * w0.x + r20.y * w0.y + r20.z * w0.z + r20.w * w0.w
             + r21.x * w1.x + r21.y * w1.y + r21.z * w1.z + r21.w * w1.w;

    // Warp butterfly reduce (all three dots in the same butterfly passes).
    #pragma unroll
    for (int off = 16; off > 0; off >>= 1) {
        d0 += __shfl_xor_sync(0xffffffffu, d0, off);
        d1 += __shfl_xor_sync(0xffffffffu, d1, off);
        d2 += __shfl_xor_sync(0xffffffffu, d2, off);
    }

    // 3-way softmax (bias cancels; subtract max for stability).
    float m  = fmaxf(d0, fmaxf(d1, d2));
    float e0 = __expf(d0 - m);
    float e1 = __expf(d1 - m);
    float e2 = __expf(d2 - m);
    float inv = 1.0f / (e0 + e1 + e2);
    float a0 = e0 * inv, a1 = e1 * inv, a2 = e2 * inv;

    // Weighted sum of the three rows.
    float4 o0, o1;
    o0.x = r00.x * a0 + r10.x * a1 + r20.x * a2;
    o0.y = r00.y * a0 + r10.y * a1 + r20.y * a2;
    o0.z = r00.z * a0 + r10.z * a1 + r20.z * a2;
    o0.w = r00.w * a0 + r10.w * a1 + r20.w * a2;
    o1.x = r01.x * a0 + r11.x * a1 + r21.x * a2;
    o1.y = r01.y * a0 + r11.y * a1 + r21.y * a2;
    o1.z = r01.z * a0 + r11.z * a1 + r21.z * a2;
    o1.w = r01.w * a0 + r11.w * a1 + r21.w * a2;

    float4* __restrict__ op = reinterpret_cast<float4*>(out + (size_t)warp_global * F);
    op[lane]      = o0;
    op[lane + 32] = o1;
}

extern "C" void kernel_launch(void* const* d_in, const int* in_sizes, int n_in,
                              void* d_out, int out_size)
{
    const float* x = (const float*)d_in[0];   // batch_rep [196608, 256]
    const float* w = (const float*)d_in[1];   // W_weight  [1, 256]
    // d_in[2] = W_bias [1] — softmax-invariant, unused.
    float* out = (float*)d_out;               // [65536, 256]

    const int B = in_sizes[0] / F;            // 196608
    const int G = B / P;                      // 65536

    const int blocks = (G + WARPS_PER_BLOCK - 1) / WARPS_PER_BLOCK;
    gap_kernel<<<blocks, THREADS>>>(x, w, out, G);
}

// round 2
// speedup vs baseline: 1.0074x; 1.0074x over previous
#include <cuda_runtime.h>
#include <cuda_bf16.h>
#include <cstdint>

// GraphAttentionPooling:
//   x: [B=196608, F=256] f32, grouped into G=65536 groups of P=3 rows.
//   scores[g,p] = dot(x[g,p,:], w) (+bias, softmax-invariant)
//   att = softmax over p; out[g,f] = sum_p att[p] * x[g,p,f]
//
// One warp per group. Lane l owns float4 chunks l and l+32 of each 256-float row.
// All 6 row-loads issued up front (MLP~6) with streaming (evict-first) policy,
// dot via shfl_xor butterfly, 3-way softmax per lane, 2x streaming STG.128 out.

#define F 256
#define P 3
#define F4 (F / 4)            // 64 float4 per row
#define WARPS_PER_BLOCK 8
#define THREADS (WARPS_PER_BLOCK * 32)

__global__ __launch_bounds__(THREADS, 6)
void gap_kernel(const float* __restrict__ x,
                const float* __restrict__ w,
                float* __restrict__ out,
                int G)
{
    const int warp_global = (blockIdx.x * WARPS_PER_BLOCK) + (threadIdx.x >> 5);
    const int lane = threadIdx.x & 31;
    if (warp_global >= G) return;

    const size_t base = (size_t)warp_global * (size_t)(P * F);
    const float4* __restrict__ xr = reinterpret_cast<const float4*>(x + base);
    const float4* __restrict__ w4 = reinterpret_cast<const float4*>(w);

    // Front-batch all global loads for max MLP. Streaming loads: data is
    // touched exactly once — evict-first keeps L2 from thrashing.
    float4 r00 = __ldcs(&xr[0 * F4 + lane]);
    float4 r01 = __ldcs(&xr[0 * F4 + lane + 32]);
    float4 r10 = __ldcs(&xr[1 * F4 + lane]);
    float4 r11 = __ldcs(&xr[1 * F4 + lane + 32]);
    float4 r20 = __ldcs(&xr[2 * F4 + lane]);
    float4 r21 = __ldcs(&xr[2 * F4 + lane + 32]);
    // Weight vector is shared by every warp on the chip — cache it normally.
    float4 w0  = __ldg(&w4[lane]);
    float4 w1  = __ldg(&w4[lane + 32]);

    // Per-row partial dot products.
    float d0 = r00.x * w0.x + r00.y * w0.y + r00.z * w0.z + r00.w * w0.w
             + r01.x * w1.x + r01.y * w1.y + r01.z * w1.z + r01.w * w1.w;
    float d1 = r10.x * w0.x + r10.y * w0.y + r10.z * w0.z + r10.w * w0.w
             + r11.x * w1.x + r11.y * w1.y + r11.z * w1.z + r11.w * w1.w;
    float d2 = r20.x * w0.x + r20.y * w0.y + r20.z * w0.z + r20.w * w0.w
             + r21.x * w1.x + r21.y * w1.y + r21.z * w1.z + r21.w * w1.w;

    // Warp butterfly reduce (all three dots share the butterfly passes).
    #pragma unroll
    for (int off = 16; off > 0; off >>= 1) {
        d0 += __shfl_xor_sync(0xffffffffu, d0, off);
        d1 += __shfl_xor_sync(0xffffffffu, d1, off);
        d2 += __shfl_xor_sync(0xffffffffu, d2, off);
    }

    // 3-way softmax (bias cancels; subtract max for stability).
    float m  = fmaxf(d0, fmaxf(d1, d2));
    float e0 = __expf(d0 - m);
    float e1 = __expf(d1 - m);
    float e2 = __expf(d2 - m);
    float inv = 1.0f / (e0 + e1 + e2);
    float a0 = e0 * inv, a1 = e1 * inv, a2 = e2 * inv;

    // Weighted sum of the three rows.
    float4 o0, o1;
    o0.x = r00.x * a0 + r10.x * a1 + r20.x * a2;
    o0.y = r00.y * a0 + r10.y * a1 + r20.y * a2;
    o0.z = r00.z * a0 + r10.z * a1 + r20.z * a2;
    o0.w = r00.w * a0 + r10.w * a1 + r20.w * a2;
    o1.x = r01.x * a0 + r11.x * a1 + r21.x * a2;
    o1.y = r01.y * a0 + r11.y * a1 + r21.y * a2;
    o1.z = r01.z * a0 + r11.z * a1 + r21.z * a2;
    o1.w = r01.w * a0 + r11.w * a1 + r21.w * a2;

    float4* __restrict__ op = reinterpret_cast<float4*>(out + (size_t)warp_global * F);
    // Streaming stores: output is written once, never re-read by this kernel.
    __stcs(&op[lane],      o0);
    __stcs(&op[lane + 32], o1);
}

extern "C" void kernel_launch(void* const* d_in, const int* in_sizes, int n_in,
                              void* d_out, int out_size)
{
    const float* x = (const float*)d_in[0];   // batch_rep [196608, 256]
    const float* w = (const float*)d_in[1];   // W_weight  [1, 256]
    // d_in[2] = W_bias [1] — softmax-invariant, unused.
    float* out = (float*)d_out;               // [65536, 256]

    const int B = in_sizes[0] / F;            // 196608
    const int G = B / P;                      // 65536

    const int blocks = (G + WARPS_PER_BLOCK - 1) / WARPS_PER_BLOCK;
    gap_kernel<<<blocks, THREADS>>>(x, w, out, G);
}